// round 15
// baseline (speedup 1.0000x reference)
#include <cuda_runtime.h>
#include <cuda_fp16.h>
#include <stdint.h>

// Fixed problem shapes
#define NLAT_IN   181
#define NLON_IN   360
#define NLAT_OUT  361
#define NLON_OUT  720
#define KSIZE     3
#define CIN       16
#define COUT      16
#define NNZ_MAX   8192

#define NPTS        (NLAT_IN * NLON_IN)          // 65160
#define NPT4        (NPTS / 4)                   // 16290 point-quads
#define NRINGS      (KSIZE * NLAT_IN)            // 543
#define RING_W      (2 * NLON_IN)                // 720 (ring duplicated along lon)
#define PLANE_D     (NRINGS * RING_W)            // 390960 uint2 per plane
#define NBINS       (NLAT_OUT * 2)               // 722 (lat, parity) bins
#define SCAN_P      768
#define ENT_MAX     20480
#define SE_CAP      320                          // staged entries cap (2L)

#define NBLOCKS     444                          // 148 SMs x 3 blocks, co-resident
#define EIN_CQ      192                          // quads per einsum chunk
#define EIN_CHUNKS  85                           // ceil(16290/192)
#define EIN_UNITS   (6 * EIN_CHUNKS)             // 510 (k x cg-half x chunk)
#define EIN_BLOCKS  421                          // blocks 0..420 steal einsum units
#define CNT_BLOCKS  22                           // blocks 421..442
#define CNT_BASE    EIN_BLOCKS
#define SCAN_BID    443
#define MASTER_TGT  (EIN_BLOCKS + CNT_BLOCKS)    // 443
#define GUNITS      (NLAT_OUT * 4)               // 1444 gather units (ho, quad)

// Scratch (device globals — zero-initialized at load; no dynamic allocation)
__device__ uint2 g_xwq[4][PLANE_D];     // 4 planes x 4 packed fp16 channels (12.5 MB)
__device__ int   g_count[NBINS];
__device__ int   g_starts[NBINS + 2];
__device__ int   g_cursor[NBINS];
__device__ int2  g_entries[ENT_MAX];    // .x = ring*720 + (360-shift); .y = half2(v,v)
                                        // pad slots stay all-zero (v=0; addr t in-bounds)
__device__ unsigned g_cntA = 0;
__device__ unsigned g_scanflag = 0;
__device__ unsigned g_master = 0;
__device__ unsigned g_ework = 0;        // einsum work-stealing counter
__device__ unsigned g_work = 0;         // gather work-stealing counter
__device__ unsigned g_exit = 0;

__device__ __forceinline__ unsigned vld(unsigned* p) {
    return *((volatile unsigned*)p);
}

// Branch-free fused batch: 4 even-parity + 4 odd-parity entries, one uint2
// (4 channels) load each. 8 independent LDG.64 -> true 8-deep MLP in ~48 regs.
__device__ __forceinline__ void batch8_s(const int2* ep, int L, int j, int t,
                                         const uint2* __restrict__ plane,
                                         float* aE, float* aO)
{
    const __half2 hz = __float2half2_rn(0.0f);
    int2 e0 = ep[j + 0], e1 = ep[j + 1], e2 = ep[j + 2], e3 = ep[j + 3];
    int2 f0 = ep[L + j + 0], f1 = ep[L + j + 1], f2 = ep[L + j + 2], f3 = ep[L + j + 3];
    uint2 uE0 = __ldg(&plane[e0.x + t]);
    uint2 uE1 = __ldg(&plane[e1.x + t]);
    uint2 uE2 = __ldg(&plane[e2.x + t]);
    uint2 uE3 = __ldg(&plane[e3.x + t]);
    uint2 uO0 = __ldg(&plane[f0.x + t]);
    uint2 uO1 = __ldg(&plane[f1.x + t]);
    uint2 uO2 = __ldg(&plane[f2.x + t]);
    uint2 uO3 = __ldg(&plane[f3.x + t]);
    __half2 hE0 = hz, hE1 = hz, hO0 = hz, hO1 = hz;
    hE0 = __hfma2(*(__half2*)&e0.y, *(__half2*)&uE0.x, hE0);
    hE1 = __hfma2(*(__half2*)&e0.y, *(__half2*)&uE0.y, hE1);
    hE0 = __hfma2(*(__half2*)&e1.y, *(__half2*)&uE1.x, hE0);
    hE1 = __hfma2(*(__half2*)&e1.y, *(__half2*)&uE1.y, hE1);
    hE0 = __hfma2(*(__half2*)&e2.y, *(__half2*)&uE2.x, hE0);
    hE1 = __hfma2(*(__half2*)&e2.y, *(__half2*)&uE2.y, hE1);
    hE0 = __hfma2(*(__half2*)&e3.y, *(__half2*)&uE3.x, hE0);
    hE1 = __hfma2(*(__half2*)&e3.y, *(__half2*)&uE3.y, hE1);
    hO0 = __hfma2(*(__half2*)&f0.y, *(__half2*)&uO0.x, hO0);
    hO1 = __hfma2(*(__half2*)&f0.y, *(__half2*)&uO0.y, hO1);
    hO0 = __hfma2(*(__half2*)&f1.y, *(__half2*)&uO1.x, hO0);
    hO1 = __hfma2(*(__half2*)&f1.y, *(__half2*)&uO1.y, hO1);
    hO0 = __hfma2(*(__half2*)&f2.y, *(__half2*)&uO2.x, hO0);
    hO1 = __hfma2(*(__half2*)&f2.y, *(__half2*)&uO2.y, hO1);
    hO0 = __hfma2(*(__half2*)&f3.y, *(__half2*)&uO3.x, hO0);
    hO1 = __hfma2(*(__half2*)&f3.y, *(__half2*)&uO3.y, hO1);
    float2 f;
    f = __half22float2(hE0); aE[0] += f.x; aE[1] += f.y;
    f = __half22float2(hE1); aE[2] += f.x; aE[3] += f.y;
    f = __half22float2(hO0); aO[0] += f.x; aO[1] += f.y;
    f = __half22float2(hO1); aO[2] += f.x; aO[3] += f.y;
}

// Global-memory fallback (single parity, 4 entries).
__device__ __forceinline__ void batch4_g2(const int2* __restrict__ ep, int i, int t,
                                          const uint2* __restrict__ plane, float* acc)
{
    const __half2 hz = __float2half2_rn(0.0f);
    int2 e0 = __ldg(&ep[i + 0]);
    int2 e1 = __ldg(&ep[i + 1]);
    int2 e2 = __ldg(&ep[i + 2]);
    int2 e3 = __ldg(&ep[i + 3]);
    uint2 u0 = __ldg(&plane[e0.x + t]);
    uint2 u1 = __ldg(&plane[e1.x + t]);
    uint2 u2 = __ldg(&plane[e2.x + t]);
    uint2 u3 = __ldg(&plane[e3.x + t]);
    __half2 h0 = hz, h1 = hz;
    h0 = __hfma2(*(__half2*)&e0.y, *(__half2*)&u0.x, h0);
    h1 = __hfma2(*(__half2*)&e0.y, *(__half2*)&u0.y, h1);
    h0 = __hfma2(*(__half2*)&e1.y, *(__half2*)&u1.x, h0);
    h1 = __hfma2(*(__half2*)&e1.y, *(__half2*)&u1.y, h1);
    h0 = __hfma2(*(__half2*)&e2.y, *(__half2*)&u2.x, h0);
    h1 = __hfma2(*(__half2*)&e2.y, *(__half2*)&u2.y, h1);
    h0 = __hfma2(*(__half2*)&e3.y, *(__half2*)&u3.x, h0);
    h1 = __hfma2(*(__half2*)&e3.y, *(__half2*)&u3.y, h1);
    float2 f;
    f = __half22float2(h0); acc[0] += f.x; acc[1] += f.y;
    f = __half22float2(h1); acc[2] += f.x; acc[3] += f.y;
}

// ---------------------------------------------------------------------------
// One persistent kernel: 444 blocks, all co-resident (3/SM forced).
__global__ __launch_bounds__(384, 3) void fused_kernel(
    const float* __restrict__ x, const float* __restrict__ weight,
    const int* __restrict__ ker_idx, const int* __restrict__ row_idx,
    const int* __restrict__ col_idx, const float* __restrict__ vals,
    const float* __restrict__ bias, float* __restrict__ out, int nnz)
{
    const int b  = blockIdx.x;
    const int t  = threadIdx.x;
    const int nt = blockDim.x;   // 384

    __shared__ int   s_arena[2 * SCAN_P + NBINS];
    __shared__ float sw[64];
    __shared__ int   s_u;

    // ======================= PHASE A =======================
    if (b < EIN_BLOCKS) {
        // ---- einsum via work-stealing: unit = (k, cg-half, chunk of 192 quads) ----
        while (true) {
            __syncthreads();
            if (t == 0) s_u = (int)atomicAdd(&g_ework, 1u);
            __syncthreads();
            const int e = s_u;
            if (e >= EIN_UNITS) break;

            const int v     = e / EIN_CHUNKS;
            const int chunk = e - v * EIN_CHUNKS;
            const int k     = v >> 1;
            const int cg    = v & 1;

            if (t < 64) {
                int ci = t >> 2, cc = t & 3;   // sw4[ci] = weights for cc(+4) pairs
                // two half-rows: sw[ci*4+cc] holds cc0..3; sw[32+...] unused trick
                sw[ci * 4 + cc] = weight[((cg * 8 + cc) * CIN + ci) * KSIZE + k];
            }
            __syncthreads();
            // second half of channels loaded after first sync (reuse sw upper half)
            // NOTE: to keep one sync, load both halves above is impossible with 64
            // threads; instead use 128-entry layout below.
            // (handled by swB load right here with extra sync)
            if (t >= 64 && t < 128) {
                int tt = t - 64;
                int ci = tt >> 2, cc = tt & 3;
                // store into arena region (channels 4..7)
                ((float*)s_arena)[ci * 4 + cc] =
                    weight[((cg * 8 + 4 + cc) * CIN + ci) * KSIZE + k];
            }
            __syncthreads();

            const int g = chunk * EIN_CQ + t;
            if (t < EIN_CQ && g < NPT4) {
                const float4* __restrict__ x4  = (const float4*)x;
                const float4* __restrict__ wlo4 = (const float4*)sw;
                const float4* __restrict__ whi4 = (const float4*)s_arena;

                float4 acc[8];
                #pragma unroll
                for (int c = 0; c < 8; c++) acc[c] = make_float4(0.f, 0.f, 0.f, 0.f);

                #pragma unroll
                for (int ci = 0; ci < CIN; ci++) {
                    float4 xv  = __ldg(&x4[ci * NPT4 + g]);
                    float4 wlo = wlo4[ci];
                    float4 whi = whi4[ci];
                    acc[0].x = fmaf(wlo.x, xv.x, acc[0].x); acc[0].y = fmaf(wlo.x, xv.y, acc[0].y);
                    acc[0].z = fmaf(wlo.x, xv.z, acc[0].z); acc[0].w = fmaf(wlo.x, xv.w, acc[0].w);
                    acc[1].x = fmaf(wlo.y, xv.x, acc[1].x); acc[1].y = fmaf(wlo.y, xv.y, acc[1].y);
                    acc[1].z = fmaf(wlo.y, xv.z, acc[1].z); acc[1].w = fmaf(wlo.y, xv.w, acc[1].w);
                    acc[2].x = fmaf(wlo.z, xv.x, acc[2].x); acc[2].y = fmaf(wlo.z, xv.y, acc[2].y);
                    acc[2].z = fmaf(wlo.z, xv.z, acc[2].z); acc[2].w = fmaf(wlo.z, xv.w, acc[2].w);
                    acc[3].x = fmaf(wlo.w, xv.x, acc[3].x); acc[3].y = fmaf(wlo.w, xv.y, acc[3].y);
                    acc[3].z = fmaf(wlo.w, xv.z, acc[3].z); acc[3].w = fmaf(wlo.w, xv.w, acc[3].w);
                    acc[4].x = fmaf(whi.x, xv.x, acc[4].x); acc[4].y = fmaf(whi.x, xv.y, acc[4].y);
                    acc[4].z = fmaf(whi.x, xv.z, acc[4].z); acc[4].w = fmaf(whi.x, xv.w, acc[4].w);
                    acc[5].x = fmaf(whi.y, xv.x, acc[5].x); acc[5].y = fmaf(whi.y, xv.y, acc[5].y);
                    acc[5].z = fmaf(whi.y, xv.z, acc[5].z); acc[5].w = fmaf(whi.y, xv.w, acc[5].w);
                    acc[6].x = fmaf(whi.z, xv.x, acc[6].x); acc[6].y = fmaf(whi.z, xv.y, acc[6].y);
                    acc[6].z = fmaf(whi.z, xv.z, acc[6].z); acc[6].w = fmaf(whi.z, xv.w, acc[6].w);
                    acc[7].x = fmaf(whi.w, xv.x, acc[7].x); acc[7].y = fmaf(whi.w, xv.y, acc[7].y);
                    acc[7].z = fmaf(whi.w, xv.z, acc[7].z); acc[7].w = fmaf(whi.w, xv.w, acc[7].w);
                }

                const int g4  = g * 4;
                const int tin = g4 / NLON_IN;
                const int po  = g4 - tin * NLON_IN;
                const int rb  = (k * NLAT_IN + tin) * RING_W + po;
                uint2* __restrict__ dA = &g_xwq[2 * cg + 0][rb];
                uint2* __restrict__ dB = &g_xwq[2 * cg + 1][rb];

                #pragma unroll
                for (int p = 0; p < 4; p++) {
                    float4 a0 = acc[0], a1 = acc[1], a2 = acc[2], a3 = acc[3];
                    float4 a4 = acc[4], a5 = acc[5], a6 = acc[6], a7 = acc[7];
                    const float* pa = (const float*)&a0;  (void)pa;
                    float v0 = (&a0.x)[p], v1 = (&a1.x)[p], v2 = (&a2.x)[p], v3 = (&a3.x)[p];
                    float v4 = (&a4.x)[p], v5 = (&a5.x)[p], v6 = (&a6.x)[p], v7 = (&a7.x)[p];
                    __half2 hA0 = __floats2half2_rn(v0, v1);
                    __half2 hA1 = __floats2half2_rn(v2, v3);
                    __half2 hB0 = __floats2half2_rn(v4, v5);
                    __half2 hB1 = __floats2half2_rn(v6, v7);
                    uint2 uA = make_uint2(*(unsigned*)&hA0, *(unsigned*)&hA1);
                    uint2 uB = make_uint2(*(unsigned*)&hB0, *(unsigned*)&hB1);
                    dA[p] = uA; dA[NLON_IN + p] = uA;
                    dB[p] = uB; dB[NLON_IN + p] = uB;
                }
            }
        }
        __threadfence();
        __syncthreads();
        if (t == 0) atomicAdd(&g_master, 1u);
    }
    else if (b < CNT_BASE + CNT_BLOCKS) {
        // ---- count block: histogram my slice, then wait & scatter ----
        const int slice = b - CNT_BASE;
        const int i = slice * nt + t;
        int col = 0, hi = 0, p = 0;
        bool valid = (i < nnz);
        if (valid) {
            col = col_idx[i];
            hi  = col / NLON_OUT;
            p   = col - hi * NLON_OUT;
            atomicAdd(&g_count[hi * 2 + (p & 1)], 1);
        }
        __threadfence();
        __syncthreads();
        if (t == 0) atomicAdd(&g_cntA, 1u);

        if (t == 0) { while (vld(&g_scanflag) == 0u) __nanosleep(128); }
        __syncthreads();
        __threadfence();

        if (t < 33) {
            int bin = slice * 33 + t;
            if (bin < NBINS) g_count[bin] = 0;
        }

        if (valid) {
            int key = hi * 2 + (p & 1);
            int pos = atomicAdd(&g_cursor[key], 1);
            int base2 = (ker_idx[i] * NLAT_IN + row_idx[i]) * RING_W
                        + NLON_IN - (p >> 1);
            __half2 vh = __float2half2_rn(vals[i]);
            g_entries[pos] = make_int2(base2, (int)*(unsigned*)&vh);
        }
        __threadfence();
        __syncthreads();
        if (t == 0) atomicAdd(&g_master, 1u);
    }
    else if (b == SCAN_BID) {
        // ---- scanner: wait counts, pad BOTH parity bins of each row to a
        //      common x4 length, scan, publish ----
        if (t == 0) { while (vld(&g_cntA) < CNT_BLOCKS) __nanosleep(128); }
        __syncthreads();
        __threadfence();

        int* bufA = s_arena;
        int* bufB = s_arena + SCAN_P;
        int* scnt = s_arena + 2 * SCAN_P;

        for (int r = t; r < NLAT_OUT; r += nt) {
            int cE = g_count[2 * r];
            int cO = g_count[2 * r + 1];
            int L = (cE > cO) ? cE : cO;
            L = (L + 3) & ~3;
            bufA[2 * r] = L;  bufA[2 * r + 1] = L;
            scnt[2 * r] = L;  scnt[2 * r + 1] = L;
        }
        for (int i = NBINS + t; i < SCAN_P; i += nt) bufA[i] = 0;
        __syncthreads();
        int* src = bufA; int* dst = bufB;
        for (int off = 1; off < SCAN_P; off <<= 1) {
            for (int i = t; i < SCAN_P; i += nt) {
                int vv = src[i];
                if (i >= off) vv += src[i - off];
                dst[i] = vv;
            }
            __syncthreads();
            int* tmp = src; src = dst; dst = tmp;
        }
        for (int i = t; i < NBINS; i += nt) {
            g_starts[i + 1] = src[i];
            g_cursor[i]     = src[i] - scnt[i];
        }
        if (t == 0) g_starts[0] = 0;
        __threadfence();
        __syncthreads();
        if (t == 0) atomicExch(&g_scanflag, 1u);
    }

    // ======================= BARRIER =======================
    if (t == 0) { while (vld(&g_master) < MASTER_TGT) __nanosleep(128); }
    __syncthreads();
    __threadfence();

    // ======================= PHASE B: work-stealing gather =======================
    int2* se = (int2*)s_arena;

    while (true) {
        __syncthreads();
        if (t == 0) s_u = (int)atomicAdd(&g_work, 1u);
        __syncthreads();
        const int u = s_u;
        if (u >= GUNITS) break;

        const int ho = u >> 2;
        const int q  = u & 3;

        const int s0 = __ldg(&g_starts[2 * ho]);
        const int s2 = __ldg(&g_starts[2 * ho + 2]);
        const int n2 = s2 - s0;           // 2L
        const int L  = n2 >> 1;
        const bool fits = (n2 <= SE_CAP);

        if (fits) {
            for (int i = t; i < n2; i += nt) se[i] = g_entries[s0 + i];
        }
        __syncthreads();

        if (t >= NLON_IN) continue;

        const uint2* __restrict__ plane = g_xwq[q];

        float aE[4], aO[4];
        #pragma unroll
        for (int c = 0; c < 4; c++) { aE[c] = 0.0f; aO[c] = 0.0f; }

        if (fits) {
            for (int j = 0; j < L; j += 4)
                batch8_s(se, L, j, t, plane, aE, aO);
        } else {
            for (int j = 0; j < L; j += 4) batch4_g2(&g_entries[s0], j, t, plane, aE);
            for (int j = 0; j < L; j += 4) batch4_g2(&g_entries[s0 + L], j, t, plane, aO);
        }

        #pragma unroll
        for (int c = 0; c < 4; c++) {
            int co = q * 4 + c;
            float bb = __ldg(&bias[co]);
            float2* row = (float2*)(out + (size_t)co * (NLAT_OUT * NLON_OUT)
                                    + ho * NLON_OUT);
            row[t] = make_float2(aE[c] + bb, aO[c] + bb);
        }
    }

    // ======================= EXIT: last block resets state =======================
    __syncthreads();
    if (t == 0) {
        unsigned e = atomicAdd(&g_exit, 1u);
        if (e == NBLOCKS - 1) {
            g_master = 0u;
            g_cntA = 0u;
            g_scanflag = 0u;
            g_work = 0u;
            g_ework = 0u;
            __threadfence();
            g_exit = 0u;
        }
    }
}

// ---------------------------------------------------------------------------
extern "C" void kernel_launch(void* const* d_in, const int* in_sizes, int n_in,
                              void* d_out, int out_size) {
    const float* x       = (const float*)d_in[0];
    const float* weight  = (const float*)d_in[1];
    const float* bias    = (const float*)d_in[2];
    const int*   ker_idx = (const int*)d_in[3];
    const int*   row_idx = (const int*)d_in[4];
    const int*   col_idx = (const int*)d_in[5];
    const float* vals    = (const float*)d_in[6];
    float* out = (float*)d_out;

    int nnz = in_sizes[3];
    if (nnz > NNZ_MAX) nnz = NNZ_MAX;

    fused_kernel<<<NBLOCKS, 384>>>(x, weight, ker_idx, row_idx, col_idx, vals,
                                   bias, out, nnz);
}